// round 6
// baseline (speedup 1.0000x reference)
#include <cuda_runtime.h>

// Rz_layer, fused single kernel, loads-first, 2 tiles per CTA.
//   out = exp(-0.5i * phase(blk, d)) * (re + i*im)
//   phase(blk, d) = sum_q w[blk][q] * (1 - 2*bit_q(d))
//   E(d) = exp(-i*phase/2) = E_hi[d>>6] * E_lo[d&63]
//   out_re = E.re*r - E.im*m ; out_im = E.re*m + E.im*r
//
// Shapes: state (256, 32, 2, 4096) fp32; weights (32, 12) fp32.
// Output: (2, 256, 32, 2, 4096) fp32 -> real plane then imag plane.
//
// Each CTA (256 threads) handles 512 consecutive float4 = 2048 consecutive d
// (never crossing a dc/blk boundary). Table: 32 hi + 64 lo entries, built once
// under the shadow of FOUR up-front state loads; one barrier per CTA.
// d&63 = 4*(tid&15) is identical for both tiles -> lo factors shared.

#define NQ       12
#define DIM      4096
#define NBLOCKS  32
#define DC       2
#define BATCH    256
#define NELEM    (BATCH * NBLOCKS * DC * DIM)   // 67108864

__device__ __forceinline__ float2 cmul(float2 a, float2 b) {
    float2 r;
    r.x = fmaf(a.x, b.x, -a.y * b.y);
    r.y = fmaf(a.x, b.y,  a.y * b.x);
    return r;
}

__global__ void __launch_bounds__(256)
rz_fused_kernel(const float*  __restrict__ w,
                const float4* __restrict__ re,
                const float4* __restrict__ im,
                float4*       __restrict__ out_re,
                float4*       __restrict__ out_im) {
    __shared__ float2 s_hi[32];   // E_hi for this CTA's 32 (d>>6) values
    __shared__ float2 s_lo[64];   // E_lo for all 64 (d&63) values

    const int tid    = threadIdx.x;
    const int u_base = blockIdx.x << 9;          // first float4 index of CTA
    const int u0     = u_base + tid;
    const int u1     = u0 + 256;

    // ---- issue all four state loads FIRST (max MLP at CTA head) ----
    float4 r0 = __ldcs(&re[u0]);
    float4 m0 = __ldcs(&im[u0]);
    float4 r1 = __ldcs(&re[u1]);
    float4 m1 = __ldcs(&im[u1]);

    const int blk     = (u_base >> 11) & 31;     // invariant for whole CTA
    const int hi_base = (u_base & 1023) >> 4;    // 0 or 32

    // ---- build factor tables (96 sincos) under the load shadow ----
    if (tid < 32) {
        int j = hi_base + tid;                   // the d>>6 value
        float angle = 0.0f;
#pragma unroll
        for (int q = 0; q < 6; q++) {
            float sign = ((j >> (5 - q)) & 1) ? -0.5f : 0.5f;
            angle = fmaf(__ldg(&w[blk * NQ + q]), sign, angle);
        }
        float s, c;
        sincosf(angle, &s, &c);
        s_hi[tid] = make_float2(c, -s);          // exp(-i*angle)
    } else if (tid >= 64 && tid < 128) {
        int j = tid - 64;                        // the d&63 value
        float angle = 0.0f;
#pragma unroll
        for (int q = 0; q < 6; q++) {
            float sign = ((j >> (5 - q)) & 1) ? -0.5f : 0.5f;
            angle = fmaf(__ldg(&w[blk * NQ + 6 + q]), sign, angle);
        }
        float s, c;
        sincosf(angle, &s, &c);
        s_lo[j] = make_float2(c, -s);
    }
    __syncthreads();

    // ---- per-thread factors ----
    // tile0: d4 = (u_base&1023) + tid        -> hi idx = hi_base + (tid>>4)
    // tile1: d4 = (u_base&1023) + 256 + tid  -> hi idx = hi_base + 16 + (tid>>4)
    // both:  d&63 = 4*(tid&15)
    float2 eh0 = s_hi[(tid >> 4)];
    float2 eh1 = s_hi[16 + (tid >> 4)];
    // NOTE: s_hi indexed relative to hi_base since we stored j = hi_base + tid
    // at slot tid; slot k holds hi value (hi_base + k).

    const float4* lo4 = reinterpret_cast<const float4*>(s_lo);
    int lb = (tid & 15) << 1;
    float4 lo01 = lo4[lb];
    float4 lo23 = lo4[lb + 1];
    float2 l0 = make_float2(lo01.x, lo01.y);
    float2 l1 = make_float2(lo01.z, lo01.w);
    float2 l2 = make_float2(lo23.x, lo23.y);
    float2 l3 = make_float2(lo23.z, lo23.w);

    // ---- tile 0 ----
    {
        float2 E0 = cmul(eh0, l0), E1 = cmul(eh0, l1);
        float2 E2 = cmul(eh0, l2), E3 = cmul(eh0, l3);
        float4 orr, oii;
        orr.x = fmaf(E0.x, r0.x, -E0.y * m0.x);
        oii.x = fmaf(E0.x, m0.x,  E0.y * r0.x);
        orr.y = fmaf(E1.x, r0.y, -E1.y * m0.y);
        oii.y = fmaf(E1.x, m0.y,  E1.y * r0.y);
        orr.z = fmaf(E2.x, r0.z, -E2.y * m0.z);
        oii.z = fmaf(E2.x, m0.z,  E2.y * r0.z);
        orr.w = fmaf(E3.x, r0.w, -E3.y * m0.w);
        oii.w = fmaf(E3.x, m0.w,  E3.y * r0.w);
        __stcs(&out_re[u0], orr);
        __stcs(&out_im[u0], oii);
    }

    // ---- tile 1 ----
    {
        float2 E0 = cmul(eh1, l0), E1 = cmul(eh1, l1);
        float2 E2 = cmul(eh1, l2), E3 = cmul(eh1, l3);
        float4 orr, oii;
        orr.x = fmaf(E0.x, r1.x, -E0.y * m1.x);
        oii.x = fmaf(E0.x, m1.x,  E0.y * r1.x);
        orr.y = fmaf(E1.x, r1.y, -E1.y * m1.y);
        oii.y = fmaf(E1.x, m1.y,  E1.y * r1.y);
        orr.z = fmaf(E2.x, r1.z, -E2.y * m1.z);
        oii.z = fmaf(E2.x, m1.z,  E2.y * r1.z);
        orr.w = fmaf(E3.x, r1.w, -E3.y * m1.w);
        oii.w = fmaf(E3.x, m1.w,  E3.y * r1.w);
        __stcs(&out_re[u1], orr);
        __stcs(&out_im[u1], oii);
    }
}

extern "C" void kernel_launch(void* const* d_in, const int* in_sizes, int n_in,
                              void* d_out, int out_size) {
    // metadata order: state_re, state_im, weights — robust to the small
    // (384-element) weights tensor landing in any slot.
    const float* sre = nullptr;
    const float* sim = nullptr;
    const float* w   = nullptr;
    for (int i = 0; i < n_in; i++) {
        if (in_sizes[i] == NBLOCKS * NQ) { w = (const float*)d_in[i]; }
        else if (!sre)                   { sre = (const float*)d_in[i]; }
        else                             { sim = (const float*)d_in[i]; }
    }

    float* out = (float*)d_out;        // [0, NELEM) real, [NELEM, 2*NELEM) imag

    const int ncta = NELEM / 4 / 512;  // 32768
    rz_fused_kernel<<<ncta, 256>>>(w,
                                   (const float4*)sre,
                                   (const float4*)sim,
                                   (float4*)out,
                                   (float4*)(out + NELEM));
}

// round 7
// speedup vs baseline: 1.0035x; 1.0035x over previous
#include <cuda_runtime.h>

// Rz_layer, fused single kernel, loads-first, 512-thread CTAs.
//   out = exp(-0.5i * phase(blk, d)) * (re + i*im)
//   phase(blk, d) = sum_q w[blk][q] * (1 - 2*bit_q(d))
//   E(d) = exp(-i*phase/2) = E_hi[d>>6] * E_lo[d&63]
//   out_re = E.re*r - E.im*m ; out_im = E.re*m + E.im*r
//
// Shapes: state (256, 32, 2, 4096) fp32; weights (32, 12) fp32.
// Output: (2, 256, 32, 2, 4096) fp32 -> real plane then imag plane.
//
// One float4 per thread (keeps regs at 32 / full occupancy, like R5), but
// 512-thread CTAs: table is 32 hi + 64 lo entries built once per 2048
// elements (40% less table work per element than 256-thread CTAs), one
// barrier per 16 warps. State loads are issued before the table build so the
// sincos chain drains inside the DRAM-load shadow.

#define NQ       12
#define DIM      4096
#define NBLOCKS  32
#define DC       2
#define BATCH    256
#define NELEM    (BATCH * NBLOCKS * DC * DIM)   // 67108864

__device__ __forceinline__ float2 cmul(float2 a, float2 b) {
    float2 r;
    r.x = fmaf(a.x, b.x, -a.y * b.y);
    r.y = fmaf(a.x, b.y,  a.y * b.x);
    return r;
}

__global__ void __launch_bounds__(512)
rz_fused_kernel(const float*  __restrict__ w,
                const float4* __restrict__ re,
                const float4* __restrict__ im,
                float4*       __restrict__ out_re,
                float4*       __restrict__ out_im) {
    __shared__ float2 s_hi[32];   // E_hi for this CTA's 32 (d>>6) values
    __shared__ float2 s_lo[64];   // E_lo for all 64 (d&63) values

    const int tid    = threadIdx.x;              // 0..511
    const int u_base = blockIdx.x << 9;          // first float4 index of CTA
    const int u      = u_base + tid;

    // ---- issue state loads FIRST (latency starts now) ----
    float4 r = __ldcs(&re[u]);                   // streaming, evict-first
    float4 m = __ldcs(&im[u]);

    const int blk     = (u_base >> 11) & 31;     // invariant for whole CTA
    const int hi_base = (u_base & 1023) >> 4;    // 0 or 32

    // ---- build factor tables (96 sincos) under the load shadow ----
    if (tid < 32) {
        int j = hi_base + tid;                   // the d>>6 value
        float angle = 0.0f;
#pragma unroll
        for (int q = 0; q < 6; q++) {
            float sign = ((j >> (5 - q)) & 1) ? -0.5f : 0.5f;
            angle = fmaf(__ldg(&w[blk * NQ + q]), sign, angle);
        }
        float s, c;
        sincosf(angle, &s, &c);
        s_hi[tid] = make_float2(c, -s);          // exp(-i*angle); slot k = hi_base+k
    } else if (tid >= 64 && tid < 128) {
        int j = tid - 64;                        // the d&63 value
        float angle = 0.0f;
#pragma unroll
        for (int q = 0; q < 6; q++) {
            float sign = ((j >> (5 - q)) & 1) ? -0.5f : 0.5f;
            angle = fmaf(__ldg(&w[blk * NQ + 6 + q]), sign, angle);
        }
        float s, c;
        sincosf(angle, &s, &c);
        s_lo[j] = make_float2(c, -s);
    }
    __syncthreads();

    // ---- per-thread rotation coefficients ----
    // d4 = (u_base&1023) + tid (tid<512, u_base&1023 in {0,512} -> no carry)
    // hi slot = d4>>4 - hi_base = tid>>4 ;  d&63 = 4*(tid&15)
    float2 eh = s_hi[tid >> 4];
    const float4* lo4 = reinterpret_cast<const float4*>(s_lo);
    int lb = (tid & 15) << 1;
    float4 lo01 = lo4[lb];
    float4 lo23 = lo4[lb + 1];

    float2 E0 = cmul(eh, make_float2(lo01.x, lo01.y));
    float2 E1 = cmul(eh, make_float2(lo01.z, lo01.w));
    float2 E2 = cmul(eh, make_float2(lo23.x, lo23.y));
    float2 E3 = cmul(eh, make_float2(lo23.z, lo23.w));

    float4 orr, oii;
    orr.x = fmaf(E0.x, r.x, -E0.y * m.x);
    oii.x = fmaf(E0.x, m.x,  E0.y * r.x);
    orr.y = fmaf(E1.x, r.y, -E1.y * m.y);
    oii.y = fmaf(E1.x, m.y,  E1.y * r.y);
    orr.z = fmaf(E2.x, r.z, -E2.y * m.z);
    oii.z = fmaf(E2.x, m.z,  E2.y * r.z);
    orr.w = fmaf(E3.x, r.w, -E3.y * m.w);
    oii.w = fmaf(E3.x, m.w,  E3.y * r.w);

    __stcs(&out_re[u], orr);
    __stcs(&out_im[u], oii);
}

extern "C" void kernel_launch(void* const* d_in, const int* in_sizes, int n_in,
                              void* d_out, int out_size) {
    // metadata order: state_re, state_im, weights — robust to the small
    // (384-element) weights tensor landing in any slot.
    const float* sre = nullptr;
    const float* sim = nullptr;
    const float* w   = nullptr;
    for (int i = 0; i < n_in; i++) {
        if (in_sizes[i] == NBLOCKS * NQ) { w = (const float*)d_in[i]; }
        else if (!sre)                   { sre = (const float*)d_in[i]; }
        else                             { sim = (const float*)d_in[i]; }
    }

    float* out = (float*)d_out;        // [0, NELEM) real, [NELEM, 2*NELEM) imag

    const int ncta = NELEM / 4 / 512;  // 32768
    rz_fused_kernel<<<ncta, 512>>>(w,
                                   (const float4*)sre,
                                   (const float4*)sim,
                                   (float4*)out,
                                   (float4*)(out + NELEM));
}

// round 8
// speedup vs baseline: 1.0078x; 1.0043x over previous
#include <cuda_runtime.h>

// Rz_layer, fused single kernel, loads-first, 512-thread CTAs, fast sincos.
//   out = exp(-0.5i * phase(blk, d)) * (re + i*im)
//   phase(blk, d) = sum_q w[blk][q] * (1 - 2*bit_q(d))
//   E(d) = exp(-i*phase/2) = E_hi[d>>6] * E_lo[d&63]
//   out_re = E.re*r - E.im*m ; out_im = E.re*m + E.im*r
//
// Shapes: state (256, 32, 2, 4096) fp32; weights (32, 12) fp32.
// Output: (2, 256, 32, 2, 4096) fp32 -> real plane then imag plane.
//
// One float4 per thread (regs 32, full occupancy), 512-thread CTAs (table =
// 32 hi + 64 lo entries per 2048 elements). State loads issue before the
// table build; __sincosf (MUFU) keeps the build chain ~10x shorter than
// accurate sincosf, so the barrier releases inside the DRAM-load shadow.
// |angle| <= 6*pi/4 < 5 -> fast-path abs error ~2e-6, far under the 1e-3 gate.

#define NQ       12
#define DIM      4096
#define NBLOCKS  32
#define DC       2
#define BATCH    256
#define NELEM    (BATCH * NBLOCKS * DC * DIM)   // 67108864

__device__ __forceinline__ float2 cmul(float2 a, float2 b) {
    float2 r;
    r.x = fmaf(a.x, b.x, -a.y * b.y);
    r.y = fmaf(a.x, b.y,  a.y * b.x);
    return r;
}

__global__ void __launch_bounds__(512)
rz_fused_kernel(const float*  __restrict__ w,
                const float4* __restrict__ re,
                const float4* __restrict__ im,
                float4*       __restrict__ out_re,
                float4*       __restrict__ out_im) {
    __shared__ float2 s_hi[32];   // E_hi for this CTA's 32 (d>>6) values
    __shared__ float2 s_lo[64];   // E_lo for all 64 (d&63) values

    const int tid    = threadIdx.x;              // 0..511
    const int u_base = blockIdx.x << 9;          // first float4 index of CTA
    const int u      = u_base + tid;

    // ---- issue state loads FIRST (latency starts now) ----
    float4 r = __ldcs(&re[u]);                   // streaming, evict-first
    float4 m = __ldcs(&im[u]);

    const int blk     = (u_base >> 11) & 31;     // invariant for whole CTA
    const int hi_base = (u_base & 1023) >> 4;    // 0 or 32

    // ---- build factor tables (96 fast sincos) under the load shadow ----
    if (tid < 32) {
        int j = hi_base + tid;                   // the d>>6 value
        float angle = 0.0f;
#pragma unroll
        for (int q = 0; q < 6; q++) {
            float sign = ((j >> (5 - q)) & 1) ? -0.5f : 0.5f;
            angle = fmaf(__ldg(&w[blk * NQ + q]), sign, angle);
        }
        float s, c;
        __sincosf(angle, &s, &c);                // MUFU fast path; |angle| < 5
        s_hi[tid] = make_float2(c, -s);          // exp(-i*angle); slot k = hi_base+k
    } else if (tid >= 64 && tid < 128) {
        int j = tid - 64;                        // the d&63 value
        float angle = 0.0f;
#pragma unroll
        for (int q = 0; q < 6; q++) {
            float sign = ((j >> (5 - q)) & 1) ? -0.5f : 0.5f;
            angle = fmaf(__ldg(&w[blk * NQ + 6 + q]), sign, angle);
        }
        float s, c;
        __sincosf(angle, &s, &c);
        s_lo[j] = make_float2(c, -s);
    }
    __syncthreads();

    // ---- per-thread rotation coefficients ----
    // d4 = (u_base&1023) + tid (tid<512, u_base&1023 in {0,512} -> no carry)
    // hi slot = tid>>4 ;  d&63 = 4*(tid&15)
    float2 eh = s_hi[tid >> 4];
    const float4* lo4 = reinterpret_cast<const float4*>(s_lo);
    int lb = (tid & 15) << 1;
    float4 lo01 = lo4[lb];
    float4 lo23 = lo4[lb + 1];

    float2 E0 = cmul(eh, make_float2(lo01.x, lo01.y));
    float2 E1 = cmul(eh, make_float2(lo01.z, lo01.w));
    float2 E2 = cmul(eh, make_float2(lo23.x, lo23.y));
    float2 E3 = cmul(eh, make_float2(lo23.z, lo23.w));

    float4 orr, oii;
    orr.x = fmaf(E0.x, r.x, -E0.y * m.x);
    oii.x = fmaf(E0.x, m.x,  E0.y * r.x);
    orr.y = fmaf(E1.x, r.y, -E1.y * m.y);
    oii.y = fmaf(E1.x, m.y,  E1.y * r.y);
    orr.z = fmaf(E2.x, r.z, -E2.y * m.z);
    oii.z = fmaf(E2.x, m.z,  E2.y * r.z);
    orr.w = fmaf(E3.x, r.w, -E3.y * m.w);
    oii.w = fmaf(E3.x, m.w,  E3.y * r.w);

    __stcs(&out_re[u], orr);
    __stcs(&out_im[u], oii);
}

extern "C" void kernel_launch(void* const* d_in, const int* in_sizes, int n_in,
                              void* d_out, int out_size) {
    // metadata order: state_re, state_im, weights — robust to the small
    // (384-element) weights tensor landing in any slot.
    const float* sre = nullptr;
    const float* sim = nullptr;
    const float* w   = nullptr;
    for (int i = 0; i < n_in; i++) {
        if (in_sizes[i] == NBLOCKS * NQ) { w = (const float*)d_in[i]; }
        else if (!sre)                   { sre = (const float*)d_in[i]; }
        else                             { sim = (const float*)d_in[i]; }
    }

    float* out = (float*)d_out;        // [0, NELEM) real, [NELEM, 2*NELEM) imag

    const int ncta = NELEM / 4 / 512;  // 32768
    rz_fused_kernel<<<ncta, 512>>>(w,
                                   (const float4*)sre,
                                   (const float4*)sim,
                                   (float4*)out,
                                   (float4*)(out + NELEM));
}